// round 1
// baseline (speedup 1.0000x reference)
#include <cuda_runtime.h>

#define BATCH 4
#define NP 30000
#define BN (BATCH*NP)
#define HID 64
#define FD 256
#define R2 4096
#define NT 469   /* ceil(NP/64) */

// ---------------- scratch (no allocation allowed) ----------------
__device__ float g_net[BN*HID];          // 30.7 MB
__device__ int   g_idx[3*BN];            // per-plane bin index
__device__ float g_binsum[BATCH*R2*HID]; // pooling scratch
__device__ float g_bincnt[BATCH*R2];
__device__ float g_c[BN*FD];             // 123 MB
__device__ float g_fea[3*BATCH*R2*FD];   // 50 MB (scatter -> conv1 in; conv2 out)
__device__ float g_feb[3*BATCH*R2*FD];   // conv1 out -> conv2 in
__device__ float g_cnt3[3*BATCH*R2];
__device__ float g_wt[2*2304*FD];        // transposed conv weights [conv][ic*9+kk][oc]

// ---------------- bin indices ----------------
__device__ __forceinline__ int binof(float v){
    const float DEN = (float)(1.0 + 0.1 + 1e-6);
    float w = (v + 0.5f) / DEN;
    w = fminf(fmaxf(w, 0.0f), (float)(1.0 - 1e-6));
    return (int)(w * 64.0f);
}

__global__ void k_idx(const float* __restrict__ p){
    int i = blockIdx.x*256 + threadIdx.x;
    if(i >= BN) return;
    float x = p[i*3+0], y = p[i*3+1], z = p[i*3+2];
    int bx = binof(x), by = binof(y), bz = binof(z);
    g_idx[0*BN+i] = bx + 64*bz;  // xz
    g_idx[1*BN+i] = bx + 64*by;  // xy
    g_idx[2*BN+i] = by + 64*bz;  // yz
}

// ---------------- fused resblock (mode 0: x = p@fc_pos; mode 1/2: x = [net|pooled]) ----------------
#define SM_BLOCK ((64*132 + 64*68 + 128*68 + 64*68)*4)

__global__ void k_block(int mode, const float* __restrict__ p,
                        const float* __restrict__ fcW, const float* __restrict__ fcb,
                        const float* __restrict__ W0, const float* __restrict__ b0,
                        const float* __restrict__ W1, const float* __restrict__ b1,
                        const float* __restrict__ Ws)
{
    extern __shared__ float sm[];
    float* x_s = sm;                  // [64][132]
    float* h_s = x_s + 64*132;        // [64][68]
    float* wA  = h_s + 64*68;         // [128][68]  (W0^T then Ws^T)
    float* w1t = wA  + 128*68;        // [64][68]
    int t = threadIdx.x;
    int b = blockIdx.x / NT, tile = blockIdx.x % NT;
    int pt0 = tile*64;
    int npts = min(64, NP - pt0);

    if(mode == 0){
        for(int e=t; e<64*128; e+=256){
            int pt = e>>7, j = e&127;
            float v = 0.f;
            if(pt < npts){
                int gp = (b*NP + pt0 + pt)*3;
                v = fcb[j] + p[gp]*fcW[j*3] + p[gp+1]*fcW[j*3+1] + p[gp+2]*fcW[j*3+2];
            }
            x_s[pt*132+j] = v;
        }
    } else {
        for(int e=t; e<64*128; e+=256){
            int pt = e>>7, j = e&127;
            float v = 0.f;
            if(pt < npts){
                int gi = b*NP + pt0 + pt;
                v = (j < 64) ? g_net[gi*HID + j]
                             : g_binsum[(b*R2 + g_idx[gi])*HID + (j-64)];
            }
            x_s[pt*132+j] = v;
        }
    }
    for(int e=t; e<64*128; e+=256){ int o=e>>7, k=e&127; wA [k*68+o] = W0[e]; }
    for(int e=t; e<64*64;  e+=256){ int o=e>>6, k=e&63;  w1t[k*68+o] = W1[e]; }
    __syncthreads();

    int o0 = (t & 15)*4;
    int pbase = (t >> 4)*4;

    float acc[4][4];
    #pragma unroll
    for(int i=0;i<4;i++){ acc[i][0]=acc[i][1]=acc[i][2]=acc[i][3]=0.f; }
    #pragma unroll 4
    for(int k=0;k<128;k++){
        float4 w = *(const float4*)&wA[k*68 + o0];
        #pragma unroll
        for(int i=0;i<4;i++){
            float xv = x_s[(pbase+i)*132 + k];
            acc[i][0]+=w.x*xv; acc[i][1]+=w.y*xv; acc[i][2]+=w.z*xv; acc[i][3]+=w.w*xv;
        }
    }
    {
        float c0=b0[o0],c1=b0[o0+1],c2=b0[o0+2],c3=b0[o0+3];
        #pragma unroll
        for(int i=0;i<4;i++){
            float4 hv;
            hv.x=fmaxf(acc[i][0]+c0,0.f); hv.y=fmaxf(acc[i][1]+c1,0.f);
            hv.z=fmaxf(acc[i][2]+c2,0.f); hv.w=fmaxf(acc[i][3]+c3,0.f);
            *(float4*)&h_s[(pbase+i)*68 + o0] = hv;
        }
    }
    __syncthreads();
    for(int e=t; e<64*128; e+=256){ int o=e>>7, k=e&127; wA[k*68+o] = Ws[e]; }

    float acd[4][4];
    #pragma unroll
    for(int i=0;i<4;i++){ acd[i][0]=acd[i][1]=acd[i][2]=acd[i][3]=0.f; }
    #pragma unroll 4
    for(int k=0;k<64;k++){
        float4 w = *(const float4*)&w1t[k*68 + o0];
        #pragma unroll
        for(int i=0;i<4;i++){
            float hv = h_s[(pbase+i)*68 + k];
            acd[i][0]+=w.x*hv; acd[i][1]+=w.y*hv; acd[i][2]+=w.z*hv; acd[i][3]+=w.w*hv;
        }
    }
    {
        float c0=b1[o0],c1=b1[o0+1],c2=b1[o0+2],c3=b1[o0+3];
        #pragma unroll
        for(int i=0;i<4;i++){
            acd[i][0]=fmaxf(acd[i][0]+c0,0.f); acd[i][1]=fmaxf(acd[i][1]+c1,0.f);
            acd[i][2]=fmaxf(acd[i][2]+c2,0.f); acd[i][3]=fmaxf(acd[i][3]+c3,0.f);
        }
    }
    __syncthreads();
    #pragma unroll 4
    for(int k=0;k<128;k++){
        float4 w = *(const float4*)&wA[k*68 + o0];
        #pragma unroll
        for(int i=0;i<4;i++){
            float xv = x_s[(pbase+i)*132 + k];
            acd[i][0]+=w.x*xv; acd[i][1]+=w.y*xv; acd[i][2]+=w.z*xv; acd[i][3]+=w.w*xv;
        }
    }
    #pragma unroll
    for(int i=0;i<4;i++){
        int pt = pbase+i;
        if(pt < npts){
            float4 ov = make_float4(acd[i][0],acd[i][1],acd[i][2],acd[i][3]);
            *(float4*)&g_net[(b*NP + pt0 + pt)*HID + o0] = ov;
        }
    }
}

// ---------------- pooling scatter / normalize ----------------
__global__ void k_scatter_net(){
    int i = blockIdx.x*256 + threadIdx.x;
    if(i >= BN*HID) return;
    int ch = i & 63, pt = i >> 6;
    int b = pt / NP;
    int bin = g_idx[pt];
    atomicAdd(&g_binsum[(b*R2 + bin)*HID + ch], g_net[i]);
    if(ch == 0) atomicAdd(&g_bincnt[b*R2 + bin], 1.0f);
}

__global__ void k_poolnorm(){
    int i = blockIdx.x*256 + threadIdx.x;
    if(i >= BATCH*R2*HID) return;
    g_binsum[i] /= fmaxf(g_bincnt[i>>6], 1.0f);
}

// ---------------- fc_c: [64] -> [256] ----------------
#define SM_FCC ((64*68 + 64*260)*4)
__global__ void k_fc_c(const float* __restrict__ Wc, const float* __restrict__ bc){
    extern __shared__ float sm[];
    float* x_s = sm;             // [64][68]
    float* wct = sm + 64*68;     // [64][260]
    int t = threadIdx.x;
    int b = blockIdx.x / NT, tile = blockIdx.x % NT;
    int pt0 = tile*64, npts = min(64, NP - pt0);
    for(int e=t; e<64*64; e+=256){
        int pt = e>>6, k = e&63;
        x_s[pt*68+k] = (pt < npts) ? g_net[(b*NP+pt0+pt)*HID + k] : 0.f;
    }
    for(int e=t; e<256*64; e+=256){
        int o = e>>6, k = e&63;
        wct[k*260 + o] = Wc[e];
    }
    __syncthreads();
    int og = t & 15, pbase = (t>>4)*4;
    for(int oc=0; oc<4; oc++){
        int o0 = oc*64 + og*4;
        float acc[4][4];
        #pragma unroll
        for(int i=0;i<4;i++){ acc[i][0]=acc[i][1]=acc[i][2]=acc[i][3]=0.f; }
        #pragma unroll 4
        for(int k=0;k<64;k++){
            float4 w = *(const float4*)&wct[k*260 + o0];
            #pragma unroll
            for(int i=0;i<4;i++){
                float xv = x_s[(pbase+i)*68 + k];
                acc[i][0]+=w.x*xv; acc[i][1]+=w.y*xv; acc[i][2]+=w.z*xv; acc[i][3]+=w.w*xv;
            }
        }
        float c0=bc[o0],c1=bc[o0+1],c2=bc[o0+2],c3=bc[o0+3];
        #pragma unroll
        for(int i=0;i<4;i++){
            int pt = pbase+i;
            if(pt < npts){
                float4 ov = make_float4(acc[i][0]+c0, acc[i][1]+c1, acc[i][2]+c2, acc[i][3]+c3);
                *(float4*)&g_c[(b*NP+pt0+pt)*FD + o0] = ov;
            }
        }
    }
}

// ---------------- scatter c to 3 planes + normalize ----------------
__global__ void k_scatter_c(){
    int i = blockIdx.x*256 + threadIdx.x;
    if(i >= 3*BN*FD) return;
    int ch = i & 255, r = i >> 8;
    int pl = r / BN, pt = r - pl*BN;
    int b = pt / NP;
    int bin = g_idx[pl*BN + pt];
    atomicAdd(&g_fea[((pl*BATCH+b)*R2 + bin)*FD + ch], g_c[pt*FD + ch]);
    if(ch == 0) atomicAdd(&g_cnt3[(pl*BATCH+b)*R2 + bin], 1.0f);
}

__global__ void k_cnorm(){
    int i = blockIdx.x*256 + threadIdx.x;
    if(i >= 3*BATCH*R2*FD) return;
    g_fea[i] /= fmaxf(g_cnt3[i>>8], 1.0f);
}

// ---------------- conv weight transpose: W[oc][ic][3][3] -> g_wt[conv][ic*9+kk][oc] ----------------
__global__ void k_wtrans(const float* __restrict__ Wa, const float* __restrict__ Wb){
    int i = blockIdx.x*256 + threadIdx.x;
    if(i >= 2*256*2304) return;
    int c = i / (256*2304);
    int rem = i - c*256*2304;
    int oc = rem / 2304, icq = rem - oc*2304;
    const float* W = c ? Wb : Wa;
    g_wt[c*2304*FD + icq*FD + oc] = W[rem];
}

// ---------------- 3x3 conv 256->256 (+bias, relu), NHWC implicit GEMM ----------------
#define SM_CONV ((264*17 + 144*64)*4)
__global__ void k_conv(const float* __restrict__ in, float* __restrict__ out,
                       const float* __restrict__ wt, const float* __restrict__ bias)
{
    extern __shared__ float sm[];
    float* in_s = sm;              // [264][17] : 4 rows x 66 cols, stride 17
    float* w_s  = sm + 264*17;     // [144][64] : (kk*16+il) x oc-slice
    int t = threadIdx.x;
    int ocb = blockIdx.x & 3;
    int r = blockIdx.x >> 2;
    int rp = r & 31;
    int pb = r >> 5;               // plane*BATCH + b, 0..11
    const float* inp  = in  + pb*R2*FD;
    float*       outp = out + pb*R2*FD;
    int y0 = rp*2;
    int og = t & 15, pxg = t >> 4;
    int tr = pxg >> 3, c0 = (pxg & 7)*8;

    float acc[8][4];
    #pragma unroll
    for(int i=0;i<8;i++){ acc[i][0]=acc[i][1]=acc[i][2]=acc[i][3]=0.f; }

    for(int ic0=0; ic0<FD; ic0+=16){
        __syncthreads();
        // input patch: rows y0-1..y0+2, cols -1..64, 16 channels (zero pad at border)
        for(int e=t; e<1056; e+=256){
            int pos = e>>2, j = e&3;
            int rr = pos/66, cc = pos - rr*66;
            int yy = y0 + rr - 1, xx = cc - 1;
            float4 v = make_float4(0.f,0.f,0.f,0.f);
            if(yy >= 0 && yy < 64 && (unsigned)xx < 64u)
                v = *(const float4*)&inp[(yy*64+xx)*FD + ic0 + j*4];
            float* d = &in_s[pos*17 + j*4];
            d[0]=v.x; d[1]=v.y; d[2]=v.z; d[3]=v.w;
        }
        // weight slice
        for(int e=t; e<2304; e+=256){
            int q = e>>4, j = e&15;
            int kk = q>>4, il = q&15;
            *(float4*)&w_s[q*64 + j*4] =
                *(const float4*)&wt[((ic0+il)*9 + kk)*FD + ocb*64 + j*4];
        }
        __syncthreads();
        #pragma unroll
        for(int kk=0; kk<9; kk++){
            int ky = kk/3, kx = kk - ky*3;
            int posb = ((tr+ky)*66 + c0 + kx)*17;
            const float* ws = &w_s[kk*16*64 + og*4];
            #pragma unroll 2
            for(int il=0; il<16; il++){
                float4 w = *(const float4*)&ws[il*64];
                #pragma unroll
                for(int px=0; px<8; px++){
                    float xv = in_s[posb + px*17 + il];
                    acc[px][0]+=w.x*xv; acc[px][1]+=w.y*xv;
                    acc[px][2]+=w.z*xv; acc[px][3]+=w.w*xv;
                }
            }
        }
    }
    int o0 = ocb*64 + og*4;
    float b0v=bias[o0], b1v=bias[o0+1], b2v=bias[o0+2], b3v=bias[o0+3];
    int y = y0 + tr;
    #pragma unroll
    for(int px=0; px<8; px++){
        int x = c0 + px;
        float4 ov;
        ov.x = fmaxf(acc[px][0]+b0v, 0.f);
        ov.y = fmaxf(acc[px][1]+b1v, 0.f);
        ov.z = fmaxf(acc[px][2]+b2v, 0.f);
        ov.w = fmaxf(acc[px][3]+b3v, 0.f);
        *(float4*)&outp[(y*64+x)*FD + o0] = ov;
    }
}

// ---------------- bilinear grid sample over 3 planes, accumulate ----------------
__global__ void k_sample(const float* __restrict__ query, float* __restrict__ out){
    int gid = blockIdx.x*256 + threadIdx.x;
    int w = gid >> 5, lane = gid & 31;
    if(w >= BN) return;
    int b = w / NP;
    float q0 = query[w*3+0], q1 = query[w*3+1], q2 = query[w*3+2];
    float a0[4] = {0,0,0,0}, a1[4] = {0,0,0,0};
    #pragma unroll
    for(int pl=0; pl<3; pl++){
        float qa = (pl==2) ? q1 : q0;       // coord0 -> W
        float qb = (pl==1) ? q1 : q2;       // coord1 -> H
        float gx = qa*2.0f - 1.0f, gy = qb*2.0f - 1.0f;
        float x = ((gx + 1.0f)*64.0f - 1.0f)*0.5f;
        float y = ((gy + 1.0f)*64.0f - 1.0f)*0.5f;
        x = fminf(fmaxf(x, 0.0f), 63.0f);
        y = fminf(fmaxf(y, 0.0f), 63.0f);
        float x0f = floorf(x), y0f = floorf(y);
        int x0 = (int)x0f, y0 = (int)y0f;
        int x1 = min(x0+1, 63), y1 = min(y0+1, 63);
        float wx = x - x0f, wy = y - y0f;
        const float* f = &g_fea[(pl*BATCH + b)*R2*FD];
        float ww[4] = {(1.f-wx)*(1.f-wy), wx*(1.f-wy), (1.f-wx)*wy, wx*wy};
        int pix[4] = {y0*64+x0, y0*64+x1, y1*64+x0, y1*64+x1};
        #pragma unroll
        for(int tp=0; tp<4; tp++){
            const float* base = f + pix[tp]*FD;
            float4 v0 = *(const float4*)&base[lane*4];
            float4 v1 = *(const float4*)&base[128 + lane*4];
            float g = ww[tp];
            a0[0]+=g*v0.x; a0[1]+=g*v0.y; a0[2]+=g*v0.z; a0[3]+=g*v0.w;
            a1[0]+=g*v1.x; a1[1]+=g*v1.y; a1[2]+=g*v1.z; a1[3]+=g*v1.w;
        }
    }
    float* ob = &out[w*FD];
    *(float4*)&ob[lane*4]       = make_float4(a0[0],a0[1],a0[2],a0[3]);
    *(float4*)&ob[128+lane*4]   = make_float4(a1[0],a1[1],a1[2],a1[3]);
}

// ---------------- launch ----------------
extern "C" void kernel_launch(void* const* d_in, const int* in_sizes, int n_in,
                              void* d_out, int out_size)
{
    const float* p    = (const float*)d_in[0];
    const float* qry  = (const float*)d_in[1];
    const float* fcW  = (const float*)d_in[2];
    const float* fcb  = (const float*)d_in[3];
    const float* W0   = (const float*)d_in[4];
    const float* b0   = (const float*)d_in[5];
    const float* W1   = (const float*)d_in[6];
    const float* b1   = (const float*)d_in[7];
    const float* Ws   = (const float*)d_in[8];
    const float* Wc   = (const float*)d_in[9];
    const float* bc   = (const float*)d_in[10];
    const float* C1W  = (const float*)d_in[11];
    const float* C1b  = (const float*)d_in[12];
    const float* C2W  = (const float*)d_in[13];
    const float* C2b  = (const float*)d_in[14];
    float* out = (float*)d_out;

    cudaFuncSetAttribute(k_block, cudaFuncAttributeMaxDynamicSharedMemorySize, SM_BLOCK);
    cudaFuncSetAttribute(k_fc_c,  cudaFuncAttributeMaxDynamicSharedMemorySize, SM_FCC);
    cudaFuncSetAttribute(k_conv,  cudaFuncAttributeMaxDynamicSharedMemorySize, SM_CONV);

    void *binsum_p, *bincnt_p, *fea_p, *cnt3_p, *feb_p, *wt_p;
    cudaGetSymbolAddress(&binsum_p, g_binsum);
    cudaGetSymbolAddress(&bincnt_p, g_bincnt);
    cudaGetSymbolAddress(&fea_p,    g_fea);
    cudaGetSymbolAddress(&feb_p,    g_feb);
    cudaGetSymbolAddress(&cnt3_p,   g_cnt3);
    cudaGetSymbolAddress(&wt_p,     g_wt);

    k_idx<<<(BN+255)/256, 256>>>(p);
    k_block<<<BATCH*NT, 256, SM_BLOCK>>>(0, p, fcW, fcb, W0, b0, W1, b1, Ws);

    for(int it=1; it<=2; it++){
        cudaMemsetAsync(binsum_p, 0, (size_t)BATCH*R2*HID*4);
        cudaMemsetAsync(bincnt_p, 0, (size_t)BATCH*R2*4);
        k_scatter_net<<<(BN*HID+255)/256, 256>>>();
        k_poolnorm<<<(BATCH*R2*HID+255)/256, 256>>>();
        k_block<<<BATCH*NT, 256, SM_BLOCK>>>(it, p, fcW, fcb,
                 W0 + it*HID*128, b0 + it*HID, W1 + it*HID*HID, b1 + it*HID, Ws + it*HID*128);
    }

    k_fc_c<<<BATCH*NT, 256, SM_FCC>>>(Wc, bc);

    cudaMemsetAsync(fea_p,  0, (size_t)3*BATCH*R2*FD*4);
    cudaMemsetAsync(cnt3_p, 0, (size_t)3*BATCH*R2*4);
    k_scatter_c<<<(3*BN*FD)/256, 256>>>();
    k_cnorm<<<(3*BATCH*R2*FD)/256, 256>>>();

    k_wtrans<<<(2*256*2304)/256, 256>>>(C1W, C2W);

    k_conv<<<12*32*4, 256, SM_CONV>>>((const float*)fea_p, (float*)feb_p,
                                      (const float*)wt_p,                 C1b);
    k_conv<<<12*32*4, 256, SM_CONV>>>((const float*)feb_p, (float*)fea_p,
                                      (const float*)wt_p + 2304*FD,       C2b);

    k_sample<<<(BN*32)/256, 256>>>(qry, out);
}